// round 15
// baseline (speedup 1.0000x reference)
#include <cuda_runtime.h>
#include <cuda_fp16.h>
#include <cstdint>
#include <math.h>

using f16 = __half;

#define NB 8
#define NS 4096
#define NC 256
#define NG 32
#define CPG 8
#define KTILES 32          // NS / 128 key tiles

// ---------------- scratch ----------------------------------------------------
__device__ f16   g_hnb[(size_t)NB * NS * NC];
__device__ f16   g_qb [(size_t)NB * NS * NC];
__device__ f16   g_kb [(size_t)NB * NS * NC];
__device__ f16   g_vb [(size_t)NB * NS * NC];
__device__ f16   g_aob[(size_t)NB * NS * NC];
__device__ f16   g_wb [4 * NC * NC];
__device__ float g_mean[NB * NG];
__device__ float g_rstd[NB * NG];

// ---------------- helpers -----------------------------------------------------
__device__ __forceinline__ uint32_t smem_u32(const void* p) {
    return (uint32_t)__cvta_generic_to_shared(p);
}
__device__ __forceinline__ void ldsm4(uint32_t* r, uint32_t addr) {
    asm volatile("ldmatrix.sync.aligned.m8n8.x4.shared.b16 {%0,%1,%2,%3},[%4];"
                 : "=r"(r[0]), "=r"(r[1]), "=r"(r[2]), "=r"(r[3]) : "r"(addr));
}
__device__ __forceinline__ void ldsm4t(uint32_t* r, uint32_t addr) {
    asm volatile("ldmatrix.sync.aligned.m8n8.x4.trans.shared.b16 {%0,%1,%2,%3},[%4];"
                 : "=r"(r[0]), "=r"(r[1]), "=r"(r[2]), "=r"(r[3]) : "r"(addr));
}
__device__ __forceinline__ void mma_f32(float* c, const uint32_t* a, uint32_t b0, uint32_t b1) {
    asm volatile("mma.sync.aligned.m16n8k16.row.col.f32.f16.f16.f32 "
                 "{%0,%1,%2,%3},{%4,%5,%6,%7},{%8,%9},{%0,%1,%2,%3};"
                 : "+f"(c[0]), "+f"(c[1]), "+f"(c[2]), "+f"(c[3])
                 : "r"(a[0]), "r"(a[1]), "r"(a[2]), "r"(a[3]), "r"(b0), "r"(b1));
}
__device__ __forceinline__ void mma_f16(uint32_t* d, const uint32_t* a, uint32_t b0, uint32_t b1) {
    asm volatile("mma.sync.aligned.m16n8k16.row.col.f16.f16.f16.f16 "
                 "{%0,%1},{%2,%3,%4,%5},{%6,%7},{%0,%1};"
                 : "+r"(d[0]), "+r"(d[1])
                 : "r"(a[0]), "r"(a[1]), "r"(a[2]), "r"(a[3]), "r"(b0), "r"(b1));
}
__device__ __forceinline__ void cpa16(uint32_t dst, const void* src) {
    asm volatile("cp.async.cg.shared.global [%0], [%1], 16;" :: "r"(dst), "l"(src));
}
__device__ __forceinline__ void cpa_commit() { asm volatile("cp.async.commit_group;"); }
__device__ __forceinline__ uint32_t pack_h2(float a, float b) {
    __half2 h = __floats2half2_rn(a, b);
    return *reinterpret_cast<uint32_t*>(&h);
}
__device__ __forceinline__ uint32_t hadd2u(uint32_t a, uint32_t b) {
    uint32_t r;
    asm("add.f16x2 %0,%1,%2;" : "=r"(r) : "r"(a), "r"(b));
    return r;
}
__device__ __forceinline__ float2 h2f2(uint32_t u) {
    return __half22float2(*reinterpret_cast<__half2*>(&u));
}

// XOR-swizzled tile addressing (16B chunk granularity)
__device__ __forceinline__ uint32_t swz512B(int r, int c) {  // 512B rows, c 0..31
    return (uint32_t)(r * 512 + ((c ^ (r & 7)) << 4));
}
__device__ __forceinline__ uint32_t swz256B(int r, int c) {  // 256B rows, c 0..15
    return (uint32_t)(r * 256 + ((c ^ (r & 7)) << 4));
}
__device__ __forceinline__ uint32_t swz128B(int r, int c) {  // 128B rows, c 0..7
    return (uint32_t)(r * 128 + ((c ^ (r & 7)) << 4));
}

// ---------------- GroupNorm statistics + weight convert (one launch) -------------
__global__ __launch_bounds__(256) void gn_stats_wconv(const float* __restrict__ x,
                                                      const float* __restrict__ wq,
                                                      const float* __restrict__ wk,
                                                      const float* __restrict__ wv,
                                                      const float* __restrict__ wo,
                                                      f16* __restrict__ wb) {
    if (blockIdx.x >= 256) {
        int i = (blockIdx.x - 256) * 256 + threadIdx.x;
        int m = i >> 16, j = i & 65535;
        const float* src = (m == 0) ? wq : (m == 1) ? wk : (m == 2) ? wv : wo;
        wb[i] = __float2half_rn(src[j]);
        return;
    }
    int bg = blockIdx.x;
    int b = bg >> 5, g = bg & 31;
    const float* xp = x + (size_t)b * NS * NC + g * CPG;
    float s = 0.f, ss = 0.f;
    for (int sp = threadIdx.x; sp < NS; sp += 256) {
        const float4* p = reinterpret_cast<const float4*>(xp + (size_t)sp * NC);
        float4 a = p[0], c = p[1];
        s  += (a.x + a.y) + (a.z + a.w) + (c.x + c.y) + (c.z + c.w);
        ss += a.x*a.x + a.y*a.y + a.z*a.z + a.w*a.w
            + c.x*c.x + c.y*c.y + c.z*c.z + c.w*c.w;
    }
    #pragma unroll
    for (int o = 16; o > 0; o >>= 1) {
        s  += __shfl_xor_sync(0xffffffffu, s,  o);
        ss += __shfl_xor_sync(0xffffffffu, ss, o);
    }
    __shared__ float shs[8], shss[8];
    int w = threadIdx.x >> 5;
    if ((threadIdx.x & 31) == 0) { shs[w] = s; shss[w] = ss; }
    __syncthreads();
    if (threadIdx.x == 0) {
        float S = 0.f, SS = 0.f;
        #pragma unroll
        for (int i = 0; i < 8; ++i) { S += shs[i]; SS += shss[i]; }
        const float invn = 1.f / (float)(NS * CPG);
        float mean = S * invn;
        float var  = SS * invn - mean * mean;
        g_mean[bg] = mean;
        g_rstd[bg] = rsqrtf(var + 1e-6f);
    }
}

// ---------------- GroupNorm apply -----------------------------------------------
__global__ __launch_bounds__(256) void gn_apply_kernel(const float* __restrict__ x,
                                                       const float* __restrict__ gamma,
                                                       const float* __restrict__ beta) {
    int i4 = blockIdx.x * 256 + threadIdx.x;
    int base = i4 * 4;
    int b = base >> 20;
    int c = base & (NC - 1);
    int bg = b * NG + (c >> 3);
    float mean = g_mean[bg], rstd = g_rstd[bg];
    float4 xv = reinterpret_cast<const float4*>(x)[i4];
    float4 gv = reinterpret_cast<const float4*>(gamma)[c >> 2];
    float4 bv = reinterpret_cast<const float4*>(beta)[c >> 2];
    uint2 o;
    o.x = pack_h2((xv.x - mean) * rstd * gv.x + bv.x,
                  (xv.y - mean) * rstd * gv.y + bv.y);
    o.y = pack_h2((xv.z - mean) * rstd * gv.z + bv.z,
                  (xv.w - mean) * rstd * gv.w + bv.w);
    reinterpret_cast<uint2*>(g_hnb)[i4] = o;
}

// ---------------- fused QKV GEMM: 512 thr, BM=128, BN=128, Kc=64 -------------------
// smem/stage: A 16K + 3x W 16K = 64K; double-buffered 128K -> 1 CTA/SM, 16 warps
#define QKV_SMEM 131072

__global__ __launch_bounds__(512, 1) void mm_qkv_fused(const f16* __restrict__ A,
                                                       const f16* __restrict__ Wall,
                                                       const float* __restrict__ b0,
                                                       const float* __restrict__ b1,
                                                       const float* __restrict__ b2,
                                                       f16* o0, f16* o1, f16* o2) {
    extern __shared__ char smc[];
    int m0 = blockIdx.x * 128, n0 = blockIdx.y * 128;
    const uint32_t sb = smem_u32(smc);
    // stage layout: A @0 (16K), Wz @16384 + z*16384 (each 64 rows x 256B, swz256B)
    int tid = threadIdx.x, lane = tid & 31, wid = tid >> 5;
    int mw = wid >> 2, nw = wid & 3;                 // 4(M:32) x 4(N:32)
    int lr = lane & 15, hc = lane >> 4;

    // chunk 0 loads
    {
        uint32_t st = sb;
        for (int i = tid; i < 1024; i += 512) {      // A: 128 rows x 8 granules
            int r = i >> 3, c = i & 7;
            cpa16(st + swz128B(r, c), A + (size_t)(m0 + r) * NC + c * 8);
        }
        for (int i = tid; i < 3072; i += 512) {      // W: 3 z x 64 rows x 16 granules
            int z = i >> 10, rr = i & 1023;
            int r = rr >> 4, c = rr & 15;
            cpa16(st + 16384 + z * 16384 + swz256B(r, c),
                  Wall + (size_t)z * NC * NC + (size_t)r * NC + n0 + c * 8);
        }
        cpa_commit();
    }

    uint32_t acc[3][2][4][2] = {};
    #pragma unroll
    for (int kc = 0; kc < 4; ++kc) {
        const int buf = kc & 1;
        const uint32_t st = sb + buf * 65536;
        if (kc < 3) {
            const uint32_t sn = sb + (buf ^ 1) * 65536;
            const f16* Ak = A + (kc + 1) * 64;
            for (int i = tid; i < 1024; i += 512) {
                int r = i >> 3, c = i & 7;
                cpa16(sn + swz128B(r, c), Ak + (size_t)(m0 + r) * NC + c * 8);
            }
            for (int i = tid; i < 3072; i += 512) {
                int z = i >> 10, rr = i & 1023;
                int r = rr >> 4, c = rr & 15;
                cpa16(sn + 16384 + z * 16384 + swz256B(r, c),
                      Wall + (size_t)z * NC * NC + (size_t)((kc + 1) * 64 + r) * NC + n0 + c * 8);
            }
            cpa_commit();
            asm volatile("cp.async.wait_group 1;");
        } else {
            asm volatile("cp.async.wait_group 0;");
        }
        __syncthreads();

        #pragma unroll
        for (int k16 = 0; k16 < 4; ++k16) {
            uint32_t a[2][4];
            ldsm4(a[0], st + swz128B(mw * 32 + lr,      k16 * 2 + hc));
            ldsm4(a[1], st + swz128B(mw * 32 + 16 + lr, k16 * 2 + hc));
            #pragma unroll
            for (int z = 0; z < 3; ++z) {
                uint32_t bw[2][4];
                #pragma unroll
                for (int ng = 0; ng < 2; ++ng)
                    ldsm4t(bw[ng], st + 16384 + z * 16384 +
                           swz256B(k16 * 16 + lr, nw * 4 + ng * 2 + hc));
                #pragma unroll
                for (int mt = 0; mt < 2; ++mt)
                    #pragma unroll
                    for (int nt = 0; nt < 4; ++nt) {
                        const uint32_t* bp = bw[nt >> 1];
                        uint32_t bb0 = (nt & 1) ? bp[2] : bp[0];
                        uint32_t bb1 = (nt & 1) ? bp[3] : bp[1];
                        mma_f16(acc[z][mt][nt], a[mt], bb0, bb1);
                    }
            }
        }
        __syncthreads();
    }

    int g = lane >> 2, t2 = (lane & 3) * 2;
    #pragma unroll
    for (int z = 0; z < 3; ++z) {
        const float* bias = (z == 0) ? b0 : (z == 1) ? b1 : b2;
        f16* out = (z == 0) ? o0 : (z == 1) ? o1 : o2;
        #pragma unroll
        for (int mt = 0; mt < 2; ++mt) {
            #pragma unroll
            for (int nt = 0; nt < 4; ++nt) {
                int row = m0 + mw * 32 + mt * 16 + g;
                int col = n0 + nw * 32 + nt * 8 + t2;
                float b0f = bias[col], b1f = bias[col + 1];
                float2 lo = h2f2(acc[z][mt][nt][0]);
                float2 hi = h2f2(acc[z][mt][nt][1]);
                *reinterpret_cast<uint32_t*>(out + (size_t)row * NC + col) =
                    pack_h2(lo.x + b0f, lo.y + b1f);
                *reinterpret_cast<uint32_t*>(out + (size_t)(row + 8) * NC + col) =
                    pack_h2(hi.x + b0f, hi.y + b1f);
            }
        }
    }
}

// ---------------- mm_out: BM=128, BN=64, Kc=64 (round-7 proven) --------------------
#define GEMM_SMEM 49152

__global__ __launch_bounds__(256, 3) void mm_out(const f16* __restrict__ A,
                                                 const f16* __restrict__ W,
                                                 const float* __restrict__ bias,
                                                 const float* __restrict__ resid,
                                                 float* __restrict__ out) {
    extern __shared__ char smc[];
    int m0 = blockIdx.x * 128, n0 = blockIdx.y * 64;
    const uint32_t sb = smem_u32(smc);
    const uint32_t sa[2] = { sb,         sb + 24576 };
    const uint32_t sw[2] = { sb + 16384, sb + 40960 };
    int tid = threadIdx.x, lane = tid & 31, wid = tid >> 5;
    int mw = wid >> 1, nw = wid & 1;
    int lr = lane & 15, hc = lane >> 4;

    for (int i = tid; i < 1024; i += 256) {
        int r = i >> 3, c = i & 7;
        cpa16(sa[0] + swz128B(r, c), A + (size_t)(m0 + r) * NC + c * 8);
    }
    for (int i = tid; i < 512; i += 256) {
        int r = i >> 3, c = i & 7;
        cpa16(sw[0] + swz128B(r, c), W + (size_t)r * NC + n0 + c * 8);
    }
    cpa_commit();

    float acc[2][4][4] = {};
    #pragma unroll
    for (int kc = 0; kc < 4; ++kc) {
        const int buf = kc & 1;
        if (kc < 3) {
            const f16* Ak = A + (kc + 1) * 64;
            const f16* Wk = W + (size_t)(kc + 1) * 64 * NC;
            for (int i = tid; i < 1024; i += 256) {
                int r = i >> 3, c = i & 7;
                cpa16(sa[buf ^ 1] + swz128B(r, c), Ak + (size_t)(m0 + r) * NC + c * 8);
            }
            for (int i = tid; i < 512; i += 256) {
                int r = i >> 3, c = i & 7;
                cpa16(sw[buf ^ 1] + swz128B(r, c), Wk + (size_t)r * NC + n0 + c * 8);
            }
            cpa_commit();
            asm volatile("cp.async.wait_group 1;");
        } else {
            asm volatile("cp.async.wait_group 0;");
        }
        __syncthreads();

        #pragma unroll
        for (int k16 = 0; k16 < 4; ++k16) {
            uint32_t a[2][4];
            ldsm4(a[0], sa[buf] + swz128B(mw * 32 + lr,      k16 * 2 + hc));
            ldsm4(a[1], sa[buf] + swz128B(mw * 32 + 16 + lr, k16 * 2 + hc));
            uint32_t bw[2][4];
            #pragma unroll
            for (int ng = 0; ng < 2; ++ng)
                ldsm4t(bw[ng], sw[buf] + swz128B(k16 * 16 + lr, nw * 4 + ng * 2 + hc));
            #pragma unroll
            for (int mt = 0; mt < 2; ++mt)
                #pragma unroll
                for (int nt = 0; nt < 4; ++nt) {
                    const uint32_t* bp = bw[nt >> 1];
                    uint32_t bb0 = (nt & 1) ? bp[2] : bp[0];
                    uint32_t bb1 = (nt & 1) ? bp[3] : bp[1];
                    mma_f32(acc[mt][nt], a[mt], bb0, bb1);
                }
        }
        __syncthreads();
    }

    int g = lane >> 2, t2 = (lane & 3) * 2;
    #pragma unroll
    for (int mt = 0; mt < 2; ++mt) {
        #pragma unroll
        for (int nt = 0; nt < 4; ++nt) {
            int row = m0 + mw * 32 + mt * 16 + g;
            int col = n0 + nw * 32 + nt * 8 + t2;
            float b0f = bias[col], b1f = bias[col + 1];
            float2 r0 = *reinterpret_cast<const float2*>(resid + (size_t)row * NC + col);
            float2 r1 = *reinterpret_cast<const float2*>(resid + (size_t)(row + 8) * NC + col);
            *reinterpret_cast<float2*>(out + (size_t)row * NC + col) =
                make_float2(acc[mt][nt][0] + b0f + r0.x, acc[mt][nt][1] + b1f + r0.y);
            *reinterpret_cast<float2*>(out + (size_t)(row + 8) * NC + col) =
                make_float2(acc[mt][nt][2] + b0f + r1.x, acc[mt][nt][3] + b1f + r1.y);
        }
    }
}

// ---------------- flash attention: 512 thr, BN=128, single-buffered K/V -------------
// (round-13 proven; unchanged)
#define AO_Q  0
#define AO_K  65536
#define AO_V  131072
#define AO_P  196608
#define AO_L  229376
#define ATTN_SMEM 231424

__global__ __launch_bounds__(512, 1) void attn_hmma(const f16* __restrict__ gq,
                                                    const f16* __restrict__ gk,
                                                    const f16* __restrict__ gv,
                                                    f16* __restrict__ gao) {
    extern __shared__ char smc[];
    const uint32_t sb = smem_u32(smc);
    float* lsh = reinterpret_cast<float*>(smc + AO_L);

    const int b = blockIdx.y, q0 = blockIdx.x * 128;
    const int tid = threadIdx.x, lane = tid & 31, wid = tid >> 5;
    const int mw = wid >> 2, nw = wid & 3;
    const int pw = wid >> 3, pn = wid & 7;
    const int lr = lane & 15, hc = lane >> 4;
    const int g = lane >> 2, t2 = (lane & 3) * 2;
    const uint32_t SC2 = pack_h2(0.09016844006f, 0.09016844006f);

    const f16* qg = gq + ((size_t)b * NS + q0) * NC;
    const f16* kg = gk + (size_t)b * NS * NC;
    const f16* vg = gv + (size_t)b * NS * NC;

    for (int i = tid; i < 4096; i += 512) {
        int r = i >> 5, c = i & 31;
        cpa16(sb + AO_Q + swz512B(r, c), qg + (size_t)r * NC + c * 8);
    }
    for (int i = tid; i < 4096; i += 512) {
        int r = i >> 5, c = i & 31;
        cpa16(sb + AO_K + swz512B(r, c), kg + (size_t)r * NC + c * 8);
    }
    cpa_commit();
    asm volatile("cp.async.wait_group 0;");
    __syncthreads();

    uint32_t O16[4][4][2];
    #pragma unroll
    for (int mt = 0; mt < 4; ++mt)
        #pragma unroll
        for (int nt = 0; nt < 4; ++nt) { O16[mt][nt][0] = 0u; O16[mt][nt][1] = 0u; }
    float lacc[4] = {0.f, 0.f, 0.f, 0.f};

    for (int t = 0; t < KTILES; ++t) {
        __syncthreads();

        {
            const f16* vs = vg + (size_t)t * 128 * NC;
            for (int i = tid; i < 4096; i += 512) {
                int r = i >> 5, c = i & 31;
                cpa16(sb + AO_V + swz512B(r, c), vs + (size_t)r * NC + c * 8);
            }
            cpa_commit();
        }

        {
            uint32_t s16[2][4][2];
            #pragma unroll
            for (int mi = 0; mi < 2; ++mi)
                #pragma unroll
                for (int nt = 0; nt < 4; ++nt) { s16[mi][nt][0] = 0u; s16[mi][nt][1] = 0u; }
            #pragma unroll
            for (int k16 = 0; k16 < 16; ++k16) {
                uint32_t a[2][4];
                ldsm4(a[0], sb + AO_Q + swz512B(mw * 32 + lr,      k16 * 2 + hc));
                ldsm4(a[1], sb + AO_Q + swz512B(mw * 32 + 16 + lr, k16 * 2 + hc));
                #pragma unroll
                for (int ng = 0; ng < 2; ++ng) {
                    uint32_t kf[4];
                    ldsm4(kf, sb + AO_K + swz512B(nw * 32 + ng * 16 + lr, k16 * 2 + hc));
                    mma_f16(s16[0][2 * ng],     a[0], kf[0], kf[2]);
                    mma_f16(s16[0][2 * ng + 1], a[0], kf[1], kf[3]);
                    mma_f16(s16[1][2 * ng],     a[1], kf[0], kf[2]);
                    mma_f16(s16[1][2 * ng + 1], a[1], kf[1], kf[3]);
                }
            }
            #pragma unroll
            for (int mi = 0; mi < 2; ++mi) {
                int row0 = mw * 32 + mi * 16 + g;
                uint32_t lp[2] = {0u, 0u};
                #pragma unroll
                for (int nt = 0; nt < 4; ++nt) {
                    int chunk = nw * 4 + nt;
                    #pragma unroll
                    for (int h = 0; h < 2; ++h) {
                        uint32_t p;
                        asm("mul.f16x2 %0,%1,%2;" : "=r"(p) : "r"(s16[mi][nt][h]), "r"(SC2));
                        asm("ex2.approx.f16x2 %0,%1;" : "=r"(p) : "r"(p));
                        lp[h] = hadd2u(lp[h], p);
                        *reinterpret_cast<uint32_t*>(smc + AO_P +
                            swz256B(row0 + h * 8, chunk) + t2 * 2) = p;
                    }
                }
                #pragma unroll
                for (int h = 0; h < 2; ++h) {
                    float2 lf = h2f2(lp[h]);
                    lacc[mi * 2 + h] += lf.x + lf.y;
                }
            }
        }

        asm volatile("cp.async.wait_group 0;");
        __syncthreads();

        if (t + 1 < KTILES) {
            const f16* ks = kg + (size_t)(t + 1) * 128 * NC;
            for (int i = tid; i < 4096; i += 512) {
                int r = i >> 5, c = i & 31;
                cpa16(sb + AO_K + swz512B(r, c), ks + (size_t)r * NC + c * 8);
            }
            cpa_commit();
        }

        #pragma unroll
        for (int k16 = 0; k16 < 8; ++k16) {
            uint32_t pa[4][4];
            #pragma unroll
            for (int mt = 0; mt < 4; ++mt)
                ldsm4(pa[mt], sb + AO_P + swz256B(pw * 64 + mt * 16 + lr, k16 * 2 + hc));
            uint32_t vf[2][4];
            #pragma unroll
            for (int d = 0; d < 2; ++d)
                ldsm4t(vf[d], sb + AO_V + swz512B(k16 * 16 + lr, pn * 4 + d * 2 + hc));
            #pragma unroll
            for (int mt = 0; mt < 4; ++mt)
                #pragma unroll
                for (int nt = 0; nt < 4; ++nt) {
                    const uint32_t* bp = vf[nt >> 1];
                    uint32_t bb0 = (nt & 1) ? bp[2] : bp[0];
                    uint32_t bb1 = (nt & 1) ? bp[3] : bp[1];
                    mma_f16(O16[mt][nt], pa[mt], bb0, bb1);
                }
        }

        asm volatile("cp.async.wait_group 0;");
    }

    #pragma unroll
    for (int i = 0; i < 4; ++i) {
        lacc[i] += __shfl_xor_sync(0xffffffffu, lacc[i], 1);
        lacc[i] += __shfl_xor_sync(0xffffffffu, lacc[i], 2);
    }
    __syncthreads();
    if ((lane & 3) == 0) {
        lsh[(mw * 32 + g)      * 4 + nw] = lacc[0];
        lsh[(mw * 32 + 8 + g)  * 4 + nw] = lacc[1];
        lsh[(mw * 32 + 16 + g) * 4 + nw] = lacc[2];
        lsh[(mw * 32 + 24 + g) * 4 + nw] = lacc[3];
    }
    __syncthreads();

    #pragma unroll
    for (int mt = 0; mt < 4; ++mt) {
        #pragma unroll
        for (int h = 0; h < 2; ++h) {
            int row = pw * 64 + mt * 16 + h * 8 + g;
            float l = lsh[row * 4] + lsh[row * 4 + 1] + lsh[row * 4 + 2] + lsh[row * 4 + 3];
            float linv = 1.f / l;
            f16* op = gao + ((size_t)b * NS + q0 + row) * NC + pn * 32;
            #pragma unroll
            for (int nt = 0; nt < 4; ++nt) {
                float2 of = h2f2(O16[mt][nt][h]);
                *reinterpret_cast<uint32_t*>(op + nt * 8 + t2) =
                    pack_h2(of.x * linv, of.y * linv);
            }
        }
    }
}

// ---------------- launch ------------------------------------------------------------
extern "C" void kernel_launch(void* const* d_in, const int* in_sizes, int n_in,
                              void* d_out, int out_size) {
    const float* x      = (const float*)d_in[0];
    const float* gscale = (const float*)d_in[1];
    const float* gbias  = (const float*)d_in[2];
    const float* wq = (const float*)d_in[3];
    const float* bq = (const float*)d_in[4];
    const float* wk = (const float*)d_in[5];
    const float* bk = (const float*)d_in[6];
    const float* wv = (const float*)d_in[7];
    const float* bv = (const float*)d_in[8];
    const float* wo = (const float*)d_in[9];
    const float* bo = (const float*)d_in[10];

    f16 *hnb, *qb, *kb, *vb, *aob, *wb;
    cudaGetSymbolAddress((void**)&hnb, g_hnb);
    cudaGetSymbolAddress((void**)&qb,  g_qb);
    cudaGetSymbolAddress((void**)&kb,  g_kb);
    cudaGetSymbolAddress((void**)&vb,  g_vb);
    cudaGetSymbolAddress((void**)&aob, g_aob);
    cudaGetSymbolAddress((void**)&wb,  g_wb);

    cudaFuncSetAttribute(mm_qkv_fused, cudaFuncAttributeMaxDynamicSharedMemorySize, QKV_SMEM);
    cudaFuncSetAttribute(mm_out, cudaFuncAttributeMaxDynamicSharedMemorySize, GEMM_SMEM);
    cudaFuncSetAttribute(attn_hmma, cudaFuncAttributeMaxDynamicSharedMemorySize, ATTN_SMEM);

    gn_stats_wconv<<<256 + 1024, 256>>>(x, wq, wk, wv, wo, wb);
    gn_apply_kernel<<<(NB * NS * NC / 4) / 256, 256>>>(x, gscale, gbias);

    mm_qkv_fused<<<dim3(NB * NS / 128, NC / 128), 512, QKV_SMEM>>>(hnb, wb, bq, bk, bv, qb, kb, vb);

    attn_hmma<<<dim3(NS / 128, NB), 512, ATTN_SMEM>>>(qb, kb, vb, aob);

    mm_out<<<dim3(NB * NS / 128, NC / 64), 256, GEMM_SMEM>>>(aob, wb + 3 * NC * NC, bo, x, (float*)d_out);
}

// round 16
// speedup vs baseline: 1.0134x; 1.0134x over previous
#include <cuda_runtime.h>
#include <cuda_fp16.h>
#include <cstdint>
#include <math.h>

using f16 = __half;

#define NB 8
#define NS 4096
#define NC 256
#define NG 32
#define CPG 8
#define KTILES 32          // NS / 128 key tiles

// ---------------- scratch ----------------------------------------------------
__device__ f16   g_hnb[(size_t)NB * NS * NC];
__device__ f16   g_qb [(size_t)NB * NS * NC];
__device__ f16   g_kb [(size_t)NB * NS * NC];
__device__ f16   g_vb [(size_t)NB * NS * NC];
__device__ f16   g_aob[(size_t)NB * NS * NC];
__device__ f16   g_wb [4 * NC * NC];
__device__ float g_mean[NB * NG];
__device__ float g_rstd[NB * NG];

// ---------------- helpers -----------------------------------------------------
__device__ __forceinline__ uint32_t smem_u32(const void* p) {
    return (uint32_t)__cvta_generic_to_shared(p);
}
__device__ __forceinline__ void ldsm4(uint32_t* r, uint32_t addr) {
    asm volatile("ldmatrix.sync.aligned.m8n8.x4.shared.b16 {%0,%1,%2,%3},[%4];"
                 : "=r"(r[0]), "=r"(r[1]), "=r"(r[2]), "=r"(r[3]) : "r"(addr));
}
__device__ __forceinline__ void ldsm4t(uint32_t* r, uint32_t addr) {
    asm volatile("ldmatrix.sync.aligned.m8n8.x4.trans.shared.b16 {%0,%1,%2,%3},[%4];"
                 : "=r"(r[0]), "=r"(r[1]), "=r"(r[2]), "=r"(r[3]) : "r"(addr));
}
__device__ __forceinline__ void mma_f32(float* c, const uint32_t* a, uint32_t b0, uint32_t b1) {
    asm volatile("mma.sync.aligned.m16n8k16.row.col.f32.f16.f16.f32 "
                 "{%0,%1,%2,%3},{%4,%5,%6,%7},{%8,%9},{%0,%1,%2,%3};"
                 : "+f"(c[0]), "+f"(c[1]), "+f"(c[2]), "+f"(c[3])
                 : "r"(a[0]), "r"(a[1]), "r"(a[2]), "r"(a[3]), "r"(b0), "r"(b1));
}
__device__ __forceinline__ void mma_f16(uint32_t* d, const uint32_t* a, uint32_t b0, uint32_t b1) {
    asm volatile("mma.sync.aligned.m16n8k16.row.col.f16.f16.f16.f16 "
                 "{%0,%1},{%2,%3,%4,%5},{%6,%7},{%0,%1};"
                 : "+r"(d[0]), "+r"(d[1])
                 : "r"(a[0]), "r"(a[1]), "r"(a[2]), "r"(a[3]), "r"(b0), "r"(b1));
}
__device__ __forceinline__ void cpa16(uint32_t dst, const void* src) {
    asm volatile("cp.async.cg.shared.global [%0], [%1], 16;" :: "r"(dst), "l"(src));
}
__device__ __forceinline__ void cpa_commit() { asm volatile("cp.async.commit_group;"); }
__device__ __forceinline__ uint32_t pack_h2(float a, float b) {
    __half2 h = __floats2half2_rn(a, b);
    return *reinterpret_cast<uint32_t*>(&h);
}
__device__ __forceinline__ uint32_t hadd2u(uint32_t a, uint32_t b) {
    uint32_t r;
    asm("add.f16x2 %0,%1,%2;" : "=r"(r) : "r"(a), "r"(b));
    return r;
}
__device__ __forceinline__ float2 h2f2(uint32_t u) {
    return __half22float2(*reinterpret_cast<__half2*>(&u));
}

// XOR-swizzled tile addressing (16B chunk granularity)
__device__ __forceinline__ uint32_t swz512B(int r, int c) {  // 512B rows, c 0..31
    return (uint32_t)(r * 512 + ((c ^ (r & 7)) << 4));
}
__device__ __forceinline__ uint32_t swz256B(int r, int c) {  // 256B rows, c 0..15
    return (uint32_t)(r * 256 + ((c ^ (r & 7)) << 4));
}
__device__ __forceinline__ uint32_t swz128B(int r, int c) {  // 128B rows, c 0..7
    return (uint32_t)(r * 128 + ((c ^ (r & 7)) << 4));
}

// ---------------- GroupNorm statistics -----------------------------------------
__global__ __launch_bounds__(256) void gn_stats_kernel(const float* __restrict__ x) {
    int bg = blockIdx.x;
    int b = bg >> 5, g = bg & 31;
    const float* xp = x + (size_t)b * NS * NC + g * CPG;
    float s = 0.f, ss = 0.f;
    for (int sp = threadIdx.x; sp < NS; sp += 256) {
        const float4* p = reinterpret_cast<const float4*>(xp + (size_t)sp * NC);
        float4 a = p[0], c = p[1];
        s  += (a.x + a.y) + (a.z + a.w) + (c.x + c.y) + (c.z + c.w);
        ss += a.x*a.x + a.y*a.y + a.z*a.z + a.w*a.w
            + c.x*c.x + c.y*c.y + c.z*c.z + c.w*c.w;
    }
    #pragma unroll
    for (int o = 16; o > 0; o >>= 1) {
        s  += __shfl_xor_sync(0xffffffffu, s,  o);
        ss += __shfl_xor_sync(0xffffffffu, ss, o);
    }
    __shared__ float shs[8], shss[8];
    int w = threadIdx.x >> 5;
    if ((threadIdx.x & 31) == 0) { shs[w] = s; shss[w] = ss; }
    __syncthreads();
    if (threadIdx.x == 0) {
        float S = 0.f, SS = 0.f;
        #pragma unroll
        for (int i = 0; i < 8; ++i) { S += shs[i]; SS += shss[i]; }
        const float invn = 1.f / (float)(NS * CPG);
        float mean = S * invn;
        float var  = SS * invn - mean * mean;
        g_mean[bg] = mean;
        g_rstd[bg] = rsqrtf(var + 1e-6f);
    }
}

// ---------------- GroupNorm apply -----------------------------------------------
__global__ __launch_bounds__(256) void gn_apply_kernel(const float* __restrict__ x,
                                                       const float* __restrict__ gamma,
                                                       const float* __restrict__ beta) {
    int i4 = blockIdx.x * 256 + threadIdx.x;
    int base = i4 * 4;
    int b = base >> 20;
    int c = base & (NC - 1);
    int bg = b * NG + (c >> 3);
    float mean = g_mean[bg], rstd = g_rstd[bg];
    float4 xv = reinterpret_cast<const float4*>(x)[i4];
    float4 gv = reinterpret_cast<const float4*>(gamma)[c >> 2];
    float4 bv = reinterpret_cast<const float4*>(beta)[c >> 2];
    uint2 o;
    o.x = pack_h2((xv.x - mean) * rstd * gv.x + bv.x,
                  (xv.y - mean) * rstd * gv.y + bv.y);
    o.y = pack_h2((xv.z - mean) * rstd * gv.z + bv.z,
                  (xv.w - mean) * rstd * gv.w + bv.w);
    reinterpret_cast<uint2*>(g_hnb)[i4] = o;
}

// ---------------- weight convert -------------------------------------------------
__global__ __launch_bounds__(256) void wconv4_kernel(const float* __restrict__ a,
                                                     const float* __restrict__ b,
                                                     const float* __restrict__ c,
                                                     const float* __restrict__ d,
                                                     f16* __restrict__ out) {
    int i = blockIdx.x * 256 + threadIdx.x;
    int m = i >> 16, j = i & 65535;
    const float* src = (m == 0) ? a : (m == 1) ? b : (m == 2) ? c : d;
    out[i] = __float2half_rn(src[j]);
}

// ---------------- fused QKV GEMM: BM=128, BN=64, Kc=64, 3 outputs/CTA --------------
// smem per stage: A 16KB + 3x W 8KB = 40KB; double-buffered = 80KB -> occ 2
#define QKV_SMEM 81920

__global__ __launch_bounds__(256, 2) void mm_qkv_fused(const f16* __restrict__ A,
                                                       const f16* __restrict__ Wall,
                                                       const float* __restrict__ b0,
                                                       const float* __restrict__ b1,
                                                       const float* __restrict__ b2,
                                                       f16* o0, f16* o1, f16* o2) {
    extern __shared__ char smc[];
    int m0 = blockIdx.x * 128, n0 = blockIdx.y * 64;
    const uint32_t sb = smem_u32(smc);
    int tid = threadIdx.x, lane = tid & 31, wid = tid >> 5;
    int mw = wid >> 1, nw = wid & 1;
    int lr = lane & 15, hc = lane >> 4;

    {
        uint32_t st = sb;
        for (int i = tid; i < 1024; i += 256) {
            int r = i >> 3, c = i & 7;
            cpa16(st + swz128B(r, c), A + (size_t)(m0 + r) * NC + c * 8);
        }
        for (int i = tid; i < 1536; i += 256) {
            int z = i / 512, rr = i & 511;
            int r = rr >> 3, c = rr & 7;
            cpa16(st + 16384 + z * 8192 + swz128B(r, c),
                  Wall + (size_t)z * NC * NC + (size_t)r * NC + n0 + c * 8);
        }
        cpa_commit();
    }

    uint32_t acc[3][2][4][2] = {};
    #pragma unroll
    for (int kc = 0; kc < 4; ++kc) {
        const int buf = kc & 1;
        const uint32_t st = sb + buf * 40960;
        if (kc < 3) {
            const uint32_t sn = sb + (buf ^ 1) * 40960;
            const f16* Ak = A + (kc + 1) * 64;
            for (int i = tid; i < 1024; i += 256) {
                int r = i >> 3, c = i & 7;
                cpa16(sn + swz128B(r, c), Ak + (size_t)(m0 + r) * NC + c * 8);
            }
            for (int i = tid; i < 1536; i += 256) {
                int z = i / 512, rr = i & 511;
                int r = rr >> 3, c = rr & 7;
                cpa16(sn + 16384 + z * 8192 + swz128B(r, c),
                      Wall + (size_t)z * NC * NC + (size_t)((kc + 1) * 64 + r) * NC + n0 + c * 8);
            }
            cpa_commit();
            asm volatile("cp.async.wait_group 1;");
        } else {
            asm volatile("cp.async.wait_group 0;");
        }
        __syncthreads();

        #pragma unroll
        for (int k16 = 0; k16 < 4; ++k16) {
            uint32_t a[2][4];
            ldsm4(a[0], st + swz128B(mw * 32 + lr,      k16 * 2 + hc));
            ldsm4(a[1], st + swz128B(mw * 32 + 16 + lr, k16 * 2 + hc));
            #pragma unroll
            for (int z = 0; z < 3; ++z) {
                uint32_t bw[2][4];
                #pragma unroll
                for (int ng = 0; ng < 2; ++ng)
                    ldsm4t(bw[ng], st + 16384 + z * 8192 +
                           swz128B(k16 * 16 + lr, nw * 4 + ng * 2 + hc));
                #pragma unroll
                for (int mt = 0; mt < 2; ++mt)
                    #pragma unroll
                    for (int nt = 0; nt < 4; ++nt) {
                        const uint32_t* bp = bw[nt >> 1];
                        uint32_t bb0 = (nt & 1) ? bp[2] : bp[0];
                        uint32_t bb1 = (nt & 1) ? bp[3] : bp[1];
                        mma_f16(acc[z][mt][nt], a[mt], bb0, bb1);
                    }
            }
        }
        __syncthreads();
    }

    int g = lane >> 2, t2 = (lane & 3) * 2;
    #pragma unroll
    for (int z = 0; z < 3; ++z) {
        const float* bias = (z == 0) ? b0 : (z == 1) ? b1 : b2;
        f16* out = (z == 0) ? o0 : (z == 1) ? o1 : o2;
        #pragma unroll
        for (int mt = 0; mt < 2; ++mt) {
            #pragma unroll
            for (int nt = 0; nt < 4; ++nt) {
                int row = m0 + mw * 32 + mt * 16 + g;
                int col = n0 + nw * 32 + nt * 8 + t2;
                float b0f = bias[col], b1f = bias[col + 1];
                float2 lo = h2f2(acc[z][mt][nt][0]);
                float2 hi = h2f2(acc[z][mt][nt][1]);
                *reinterpret_cast<uint32_t*>(out + (size_t)row * NC + col) =
                    pack_h2(lo.x + b0f, lo.y + b1f);
                *reinterpret_cast<uint32_t*>(out + (size_t)(row + 8) * NC + col) =
                    pack_h2(hi.x + b0f, hi.y + b1f);
            }
        }
    }
}

// ---------------- mm_out: BM=128, BN=64, Kc=64, f16 accum, occ 4 --------------------
#define GEMM_SMEM 49152

__global__ __launch_bounds__(256, 4) void mm_out(const f16* __restrict__ A,
                                                 const f16* __restrict__ W,
                                                 const float* __restrict__ bias,
                                                 const float* __restrict__ resid,
                                                 float* __restrict__ out) {
    extern __shared__ char smc[];
    int m0 = blockIdx.x * 128, n0 = blockIdx.y * 64;
    const uint32_t sb = smem_u32(smc);
    const uint32_t sa[2] = { sb,         sb + 24576 };
    const uint32_t sw[2] = { sb + 16384, sb + 40960 };
    int tid = threadIdx.x, lane = tid & 31, wid = tid >> 5;
    int mw = wid >> 1, nw = wid & 1;
    int lr = lane & 15, hc = lane >> 4;

    for (int i = tid; i < 1024; i += 256) {
        int r = i >> 3, c = i & 7;
        cpa16(sa[0] + swz128B(r, c), A + (size_t)(m0 + r) * NC + c * 8);
    }
    for (int i = tid; i < 512; i += 256) {
        int r = i >> 3, c = i & 7;
        cpa16(sw[0] + swz128B(r, c), W + (size_t)r * NC + n0 + c * 8);
    }
    cpa_commit();

    uint32_t acc[2][4][2] = {};
    #pragma unroll
    for (int kc = 0; kc < 4; ++kc) {
        const int buf = kc & 1;
        if (kc < 3) {
            const f16* Ak = A + (kc + 1) * 64;
            const f16* Wk = W + (size_t)(kc + 1) * 64 * NC;
            for (int i = tid; i < 1024; i += 256) {
                int r = i >> 3, c = i & 7;
                cpa16(sa[buf ^ 1] + swz128B(r, c), Ak + (size_t)(m0 + r) * NC + c * 8);
            }
            for (int i = tid; i < 512; i += 256) {
                int r = i >> 3, c = i & 7;
                cpa16(sw[buf ^ 1] + swz128B(r, c), Wk + (size_t)r * NC + n0 + c * 8);
            }
            cpa_commit();
            asm volatile("cp.async.wait_group 1;");
        } else {
            asm volatile("cp.async.wait_group 0;");
        }
        __syncthreads();

        #pragma unroll
        for (int k16 = 0; k16 < 4; ++k16) {
            uint32_t a[2][4];
            ldsm4(a[0], sa[buf] + swz128B(mw * 32 + lr,      k16 * 2 + hc));
            ldsm4(a[1], sa[buf] + swz128B(mw * 32 + 16 + lr, k16 * 2 + hc));
            uint32_t bw[2][4];
            #pragma unroll
            for (int ng = 0; ng < 2; ++ng)
                ldsm4t(bw[ng], sw[buf] + swz128B(k16 * 16 + lr, nw * 4 + ng * 2 + hc));
            #pragma unroll
            for (int mt = 0; mt < 2; ++mt)
                #pragma unroll
                for (int nt = 0; nt < 4; ++nt) {
                    const uint32_t* bp = bw[nt >> 1];
                    uint32_t bb0 = (nt & 1) ? bp[2] : bp[0];
                    uint32_t bb1 = (nt & 1) ? bp[3] : bp[1];
                    mma_f16(acc[mt][nt], a[mt], bb0, bb1);
                }
        }
        __syncthreads();
    }

    int g = lane >> 2, t2 = (lane & 3) * 2;
    #pragma unroll
    for (int mt = 0; mt < 2; ++mt) {
        #pragma unroll
        for (int nt = 0; nt < 4; ++nt) {
            int row = m0 + mw * 32 + mt * 16 + g;
            int col = n0 + nw * 32 + nt * 8 + t2;
            float b0f = bias[col], b1f = bias[col + 1];
            float2 lo = h2f2(acc[mt][nt][0]);
            float2 hi = h2f2(acc[mt][nt][1]);
            float2 r0 = *reinterpret_cast<const float2*>(resid + (size_t)row * NC + col);
            float2 r1 = *reinterpret_cast<const float2*>(resid + (size_t)(row + 8) * NC + col);
            *reinterpret_cast<float2*>(out + (size_t)row * NC + col) =
                make_float2(lo.x + b0f + r0.x, lo.y + b1f + r0.y);
            *reinterpret_cast<float2*>(out + (size_t)(row + 8) * NC + col) =
                make_float2(hi.x + b0f + r1.x, hi.y + b1f + r1.y);
        }
    }
}

// ---------------- flash attention: 512 thr, BN=128, single-buffered K/V -------------
// (round-13 proven; unchanged)
#define AO_Q  0
#define AO_K  65536
#define AO_V  131072
#define AO_P  196608
#define AO_L  229376
#define ATTN_SMEM 231424

__global__ __launch_bounds__(512, 1) void attn_hmma(const f16* __restrict__ gq,
                                                    const f16* __restrict__ gk,
                                                    const f16* __restrict__ gv,
                                                    f16* __restrict__ gao) {
    extern __shared__ char smc[];
    const uint32_t sb = smem_u32(smc);
    float* lsh = reinterpret_cast<float*>(smc + AO_L);

    const int b = blockIdx.y, q0 = blockIdx.x * 128;
    const int tid = threadIdx.x, lane = tid & 31, wid = tid >> 5;
    const int mw = wid >> 2, nw = wid & 3;
    const int pw = wid >> 3, pn = wid & 7;
    const int lr = lane & 15, hc = lane >> 4;
    const int g = lane >> 2, t2 = (lane & 3) * 2;
    const uint32_t SC2 = pack_h2(0.09016844006f, 0.09016844006f);

    const f16* qg = gq + ((size_t)b * NS + q0) * NC;
    const f16* kg = gk + (size_t)b * NS * NC;
    const f16* vg = gv + (size_t)b * NS * NC;

    for (int i = tid; i < 4096; i += 512) {
        int r = i >> 5, c = i & 31;
        cpa16(sb + AO_Q + swz512B(r, c), qg + (size_t)r * NC + c * 8);
    }
    for (int i = tid; i < 4096; i += 512) {
        int r = i >> 5, c = i & 31;
        cpa16(sb + AO_K + swz512B(r, c), kg + (size_t)r * NC + c * 8);
    }
    cpa_commit();
    asm volatile("cp.async.wait_group 0;");
    __syncthreads();

    uint32_t O16[4][4][2];
    #pragma unroll
    for (int mt = 0; mt < 4; ++mt)
        #pragma unroll
        for (int nt = 0; nt < 4; ++nt) { O16[mt][nt][0] = 0u; O16[mt][nt][1] = 0u; }
    float lacc[4] = {0.f, 0.f, 0.f, 0.f};

    for (int t = 0; t < KTILES; ++t) {
        __syncthreads();

        {
            const f16* vs = vg + (size_t)t * 128 * NC;
            for (int i = tid; i < 4096; i += 512) {
                int r = i >> 5, c = i & 31;
                cpa16(sb + AO_V + swz512B(r, c), vs + (size_t)r * NC + c * 8);
            }
            cpa_commit();
        }

        {
            uint32_t s16[2][4][2];
            #pragma unroll
            for (int mi = 0; mi < 2; ++mi)
                #pragma unroll
                for (int nt = 0; nt < 4; ++nt) { s16[mi][nt][0] = 0u; s16[mi][nt][1] = 0u; }
            #pragma unroll
            for (int k16 = 0; k16 < 16; ++k16) {
                uint32_t a[2][4];
                ldsm4(a[0], sb + AO_Q + swz512B(mw * 32 + lr,      k16 * 2 + hc));
                ldsm4(a[1], sb + AO_Q + swz512B(mw * 32 + 16 + lr, k16 * 2 + hc));
                #pragma unroll
                for (int ng = 0; ng < 2; ++ng) {
                    uint32_t kf[4];
                    ldsm4(kf, sb + AO_K + swz512B(nw * 32 + ng * 16 + lr, k16 * 2 + hc));
                    mma_f16(s16[0][2 * ng],     a[0], kf[0], kf[2]);
                    mma_f16(s16[0][2 * ng + 1], a[0], kf[1], kf[3]);
                    mma_f16(s16[1][2 * ng],     a[1], kf[0], kf[2]);
                    mma_f16(s16[1][2 * ng + 1], a[1], kf[1], kf[3]);
                }
            }
            #pragma unroll
            for (int mi = 0; mi < 2; ++mi) {
                int row0 = mw * 32 + mi * 16 + g;
                uint32_t lp[2] = {0u, 0u};
                #pragma unroll
                for (int nt = 0; nt < 4; ++nt) {
                    int chunk = nw * 4 + nt;
                    #pragma unroll
                    for (int h = 0; h < 2; ++h) {
                        uint32_t p;
                        asm("mul.f16x2 %0,%1,%2;" : "=r"(p) : "r"(s16[mi][nt][h]), "r"(SC2));
                        asm("ex2.approx.f16x2 %0,%1;" : "=r"(p) : "r"(p));
                        lp[h] = hadd2u(lp[h], p);
                        *reinterpret_cast<uint32_t*>(smc + AO_P +
                            swz256B(row0 + h * 8, chunk) + t2 * 2) = p;
                    }
                }
                #pragma unroll
                for (int h = 0; h < 2; ++h) {
                    float2 lf = h2f2(lp[h]);
                    lacc[mi * 2 + h] += lf.x + lf.y;
                }
            }
        }

        asm volatile("cp.async.wait_group 0;");
        __syncthreads();

        if (t + 1 < KTILES) {
            const f16* ks = kg + (size_t)(t + 1) * 128 * NC;
            for (int i = tid; i < 4096; i += 512) {
                int r = i >> 5, c = i & 31;
                cpa16(sb + AO_K + swz512B(r, c), ks + (size_t)r * NC + c * 8);
            }
            cpa_commit();
        }

        #pragma unroll
        for (int k16 = 0; k16 < 8; ++k16) {
            uint32_t pa[4][4];
            #pragma unroll
            for (int mt = 0; mt < 4; ++mt)
                ldsm4(pa[mt], sb + AO_P + swz256B(pw * 64 + mt * 16 + lr, k16 * 2 + hc));
            uint32_t vf[2][4];
            #pragma unroll
            for (int d = 0; d < 2; ++d)
                ldsm4t(vf[d], sb + AO_V + swz512B(k16 * 16 + lr, pn * 4 + d * 2 + hc));
            #pragma unroll
            for (int mt = 0; mt < 4; ++mt)
                #pragma unroll
                for (int nt = 0; nt < 4; ++nt) {
                    const uint32_t* bp = vf[nt >> 1];
                    uint32_t bb0 = (nt & 1) ? bp[2] : bp[0];
                    uint32_t bb1 = (nt & 1) ? bp[3] : bp[1];
                    mma_f16(O16[mt][nt], pa[mt], bb0, bb1);
                }
        }

        asm volatile("cp.async.wait_group 0;");
    }

    #pragma unroll
    for (int i = 0; i < 4; ++i) {
        lacc[i] += __shfl_xor_sync(0xffffffffu, lacc[i], 1);
        lacc[i] += __shfl_xor_sync(0xffffffffu, lacc[i], 2);
    }
    __syncthreads();
    if ((lane & 3) == 0) {
        lsh[(mw * 32 + g)      * 4 + nw] = lacc[0];
        lsh[(mw * 32 + 8 + g)  * 4 + nw] = lacc[1];
        lsh[(mw * 32 + 16 + g) * 4 + nw] = lacc[2];
        lsh[(mw * 32 + 24 + g) * 4 + nw] = lacc[3];
    }
    __syncthreads();

    #pragma unroll
    for (int mt = 0; mt < 4; ++mt) {
        #pragma unroll
        for (int h = 0; h < 2; ++h) {
            int row = pw * 64 + mt * 16 + h * 8 + g;
            float l = lsh[row * 4] + lsh[row * 4 + 1] + lsh[row * 4 + 2] + lsh[row * 4 + 3];
            float linv = 1.f / l;
            f16* op = gao + ((size_t)b * NS + q0 + row) * NC + pn * 32;
            #pragma unroll
            for (int nt = 0; nt < 4; ++nt) {
                float2 of = h2f2(O16[mt][nt][h]);
                *reinterpret_cast<uint32_t*>(op + nt * 8 + t2) =
                    pack_h2(of.x * linv, of.y * linv);
            }
        }
    }
}

// ---------------- launch ------------------------------------------------------------
extern "C" void kernel_launch(void* const* d_in, const int* in_sizes, int n_in,
                              void* d_out, int out_size) {
    const float* x      = (const float*)d_in[0];
    const float* gscale = (const float*)d_in[1];
    const float* gbias  = (const float*)d_in[2];
    const float* wq = (const float*)d_in[3];
    const float* bq = (const float*)d_in[4];
    const float* wk = (const float*)d_in[5];
    const float* bk = (const float*)d_in[6];
    const float* wv = (const float*)d_in[7];
    const float* bv = (const float*)d_in[8];
    const float* wo = (const float*)d_in[9];
    const float* bo = (const float*)d_in[10];

    f16 *hnb, *qb, *kb, *vb, *aob, *wb;
    cudaGetSymbolAddress((void**)&hnb, g_hnb);
    cudaGetSymbolAddress((void**)&qb,  g_qb);
    cudaGetSymbolAddress((void**)&kb,  g_kb);
    cudaGetSymbolAddress((void**)&vb,  g_vb);
    cudaGetSymbolAddress((void**)&aob, g_aob);
    cudaGetSymbolAddress((void**)&wb,  g_wb);

    cudaFuncSetAttribute(mm_qkv_fused, cudaFuncAttributeMaxDynamicSharedMemorySize, QKV_SMEM);
    cudaFuncSetAttribute(mm_out, cudaFuncAttributeMaxDynamicSharedMemorySize, GEMM_SMEM);
    cudaFuncSetAttribute(attn_hmma, cudaFuncAttributeMaxDynamicSharedMemorySize, ATTN_SMEM);

    wconv4_kernel<<<1024, 256>>>(wq, wk, wv, wo, wb);
    gn_stats_kernel<<<NB * NG, 256>>>(x);
    gn_apply_kernel<<<(NB * NS * NC / 4) / 256, 256>>>(x, gscale, gbias);

    mm_qkv_fused<<<dim3(NB * NS / 128, NC / 64), 256, QKV_SMEM>>>(hnb, wb, bq, bk, bv, qb, kb, vb);

    attn_hmma<<<dim3(NS / 128, NB), 512, ATTN_SMEM>>>(qb, kb, vb, aob);

    mm_out<<<dim3(NB * NS / 128, NC / 64), 256, GEMM_SMEM>>>(aob, wb + 3 * NC * NC, bo, x, (float*)d_out);
}

// round 17
// speedup vs baseline: 1.0194x; 1.0059x over previous
#include <cuda_runtime.h>
#include <cuda_fp16.h>
#include <cstdint>
#include <math.h>

using f16 = __half;

#define NB 8
#define NS 4096
#define NC 256
#define NG 32
#define CPG 8
#define KTILES 32          // NS / 128 key tiles

// ---------------- scratch ----------------------------------------------------
__device__ f16   g_hnb[(size_t)NB * NS * NC];
__device__ f16   g_qb [(size_t)NB * NS * NC];
__device__ f16   g_kb [(size_t)NB * NS * NC];
__device__ f16   g_vb [(size_t)NB * NS * NC];
__device__ f16   g_aob[(size_t)NB * NS * NC];
__device__ f16   g_wb [4 * NC * NC];
__device__ float g_mean[NB * NG];
__device__ float g_rstd[NB * NG];

// ---------------- helpers -----------------------------------------------------
__device__ __forceinline__ uint32_t smem_u32(const void* p) {
    return (uint32_t)__cvta_generic_to_shared(p);
}
__device__ __forceinline__ void ldsm4(uint32_t* r, uint32_t addr) {
    asm volatile("ldmatrix.sync.aligned.m8n8.x4.shared.b16 {%0,%1,%2,%3},[%4];"
                 : "=r"(r[0]), "=r"(r[1]), "=r"(r[2]), "=r"(r[3]) : "r"(addr));
}
__device__ __forceinline__ void ldsm4t(uint32_t* r, uint32_t addr) {
    asm volatile("ldmatrix.sync.aligned.m8n8.x4.trans.shared.b16 {%0,%1,%2,%3},[%4];"
                 : "=r"(r[0]), "=r"(r[1]), "=r"(r[2]), "=r"(r[3]) : "r"(addr));
}
__device__ __forceinline__ void mma_f32(float* c, const uint32_t* a, uint32_t b0, uint32_t b1) {
    asm volatile("mma.sync.aligned.m16n8k16.row.col.f32.f16.f16.f32 "
                 "{%0,%1,%2,%3},{%4,%5,%6,%7},{%8,%9},{%0,%1,%2,%3};"
                 : "+f"(c[0]), "+f"(c[1]), "+f"(c[2]), "+f"(c[3])
                 : "r"(a[0]), "r"(a[1]), "r"(a[2]), "r"(a[3]), "r"(b0), "r"(b1));
}
__device__ __forceinline__ void mma_f16(uint32_t* d, const uint32_t* a, uint32_t b0, uint32_t b1) {
    asm volatile("mma.sync.aligned.m16n8k16.row.col.f16.f16.f16.f16 "
                 "{%0,%1},{%2,%3,%4,%5},{%6,%7},{%0,%1};"
                 : "+r"(d[0]), "+r"(d[1])
                 : "r"(a[0]), "r"(a[1]), "r"(a[2]), "r"(a[3]), "r"(b0), "r"(b1));
}
__device__ __forceinline__ void cpa16(uint32_t dst, const void* src) {
    asm volatile("cp.async.cg.shared.global [%0], [%1], 16;" :: "r"(dst), "l"(src));
}
__device__ __forceinline__ void cpa_commit() { asm volatile("cp.async.commit_group;"); }
__device__ __forceinline__ uint32_t pack_h2(float a, float b) {
    __half2 h = __floats2half2_rn(a, b);
    return *reinterpret_cast<uint32_t*>(&h);
}
__device__ __forceinline__ uint32_t hadd2u(uint32_t a, uint32_t b) {
    uint32_t r;
    asm("add.f16x2 %0,%1,%2;" : "=r"(r) : "r"(a), "r"(b));
    return r;
}
__device__ __forceinline__ float2 h2f2(uint32_t u) {
    return __half22float2(*reinterpret_cast<__half2*>(&u));
}

// XOR-swizzled tile addressing (16B chunk granularity)
__device__ __forceinline__ uint32_t swz512B(int r, int c) {  // 512B rows, c 0..31
    return (uint32_t)(r * 512 + ((c ^ (r & 7)) << 4));
}
__device__ __forceinline__ uint32_t swz256B(int r, int c) {  // 256B rows, c 0..15
    return (uint32_t)(r * 256 + ((c ^ (r & 7)) << 4));
}
__device__ __forceinline__ uint32_t swz128B(int r, int c) {  // 128B rows, c 0..7
    return (uint32_t)(r * 128 + ((c ^ (r & 7)) << 4));
}

// ---------------- GroupNorm statistics -----------------------------------------
__global__ __launch_bounds__(256) void gn_stats_kernel(const float* __restrict__ x) {
    int bg = blockIdx.x;
    int b = bg >> 5, g = bg & 31;
    const float* xp = x + (size_t)b * NS * NC + g * CPG;
    float s = 0.f, ss = 0.f;
    for (int sp = threadIdx.x; sp < NS; sp += 256) {
        const float4* p = reinterpret_cast<const float4*>(xp + (size_t)sp * NC);
        float4 a = p[0], c = p[1];
        s  += (a.x + a.y) + (a.z + a.w) + (c.x + c.y) + (c.z + c.w);
        ss += a.x*a.x + a.y*a.y + a.z*a.z + a.w*a.w
            + c.x*c.x + c.y*c.y + c.z*c.z + c.w*c.w;
    }
    #pragma unroll
    for (int o = 16; o > 0; o >>= 1) {
        s  += __shfl_xor_sync(0xffffffffu, s,  o);
        ss += __shfl_xor_sync(0xffffffffu, ss, o);
    }
    __shared__ float shs[8], shss[8];
    int w = threadIdx.x >> 5;
    if ((threadIdx.x & 31) == 0) { shs[w] = s; shss[w] = ss; }
    __syncthreads();
    if (threadIdx.x == 0) {
        float S = 0.f, SS = 0.f;
        #pragma unroll
        for (int i = 0; i < 8; ++i) { S += shs[i]; SS += shss[i]; }
        const float invn = 1.f / (float)(NS * CPG);
        float mean = S * invn;
        float var  = SS * invn - mean * mean;
        g_mean[bg] = mean;
        g_rstd[bg] = rsqrtf(var + 1e-6f);
    }
}

// ---------------- GroupNorm apply + weight convert (fused grid) -------------------
// blocks [0, 8192): gn apply; blocks [8192, 9216): weight convert
__global__ __launch_bounds__(256) void gn_apply_wconv(const float* __restrict__ x,
                                                      const float* __restrict__ gamma,
                                                      const float* __restrict__ beta,
                                                      const float* __restrict__ wq,
                                                      const float* __restrict__ wk,
                                                      const float* __restrict__ wv,
                                                      const float* __restrict__ wo,
                                                      f16* __restrict__ wb) {
    if (blockIdx.x >= 8192) {
        int i = (blockIdx.x - 8192) * 256 + threadIdx.x;
        int m = i >> 16, j = i & 65535;
        const float* src = (m == 0) ? wq : (m == 1) ? wk : (m == 2) ? wv : wo;
        wb[i] = __float2half_rn(src[j]);
        return;
    }
    int i4 = blockIdx.x * 256 + threadIdx.x;
    int base = i4 * 4;
    int b = base >> 20;
    int c = base & (NC - 1);
    int bg = b * NG + (c >> 3);
    float mean = g_mean[bg], rstd = g_rstd[bg];
    float4 xv = reinterpret_cast<const float4*>(x)[i4];
    float4 gv = reinterpret_cast<const float4*>(gamma)[c >> 2];
    float4 bv = reinterpret_cast<const float4*>(beta)[c >> 2];
    uint2 o;
    o.x = pack_h2((xv.x - mean) * rstd * gv.x + bv.x,
                  (xv.y - mean) * rstd * gv.y + bv.y);
    o.y = pack_h2((xv.z - mean) * rstd * gv.z + bv.z,
                  (xv.w - mean) * rstd * gv.w + bv.w);
    reinterpret_cast<uint2*>(g_hnb)[i4] = o;
}

// ---------------- fused QKV GEMM: BM=128, BN=64, Kc=64, 3 outputs/CTA --------------
// smem per stage: A 16KB + 3x W 8KB = 40KB; double-buffered = 80KB -> occ 2
#define QKV_SMEM 81920

__global__ __launch_bounds__(256, 2) void mm_qkv_fused(const f16* __restrict__ A,
                                                       const f16* __restrict__ Wall,
                                                       const float* __restrict__ b0,
                                                       const float* __restrict__ b1,
                                                       const float* __restrict__ b2,
                                                       f16* o0, f16* o1, f16* o2) {
    extern __shared__ char smc[];
    int m0 = blockIdx.x * 128, n0 = blockIdx.y * 64;
    const uint32_t sb = smem_u32(smc);
    int tid = threadIdx.x, lane = tid & 31, wid = tid >> 5;
    int mw = wid >> 1, nw = wid & 1;
    int lr = lane & 15, hc = lane >> 4;

    {
        uint32_t st = sb;
        for (int i = tid; i < 1024; i += 256) {
            int r = i >> 3, c = i & 7;
            cpa16(st + swz128B(r, c), A + (size_t)(m0 + r) * NC + c * 8);
        }
        for (int i = tid; i < 1536; i += 256) {
            int z = i / 512, rr = i & 511;
            int r = rr >> 3, c = rr & 7;
            cpa16(st + 16384 + z * 8192 + swz128B(r, c),
                  Wall + (size_t)z * NC * NC + (size_t)r * NC + n0 + c * 8);
        }
        cpa_commit();
    }

    uint32_t acc[3][2][4][2] = {};
    #pragma unroll
    for (int kc = 0; kc < 4; ++kc) {
        const int buf = kc & 1;
        const uint32_t st = sb + buf * 40960;
        if (kc < 3) {
            const uint32_t sn = sb + (buf ^ 1) * 40960;
            const f16* Ak = A + (kc + 1) * 64;
            for (int i = tid; i < 1024; i += 256) {
                int r = i >> 3, c = i & 7;
                cpa16(sn + swz128B(r, c), Ak + (size_t)(m0 + r) * NC + c * 8);
            }
            for (int i = tid; i < 1536; i += 256) {
                int z = i / 512, rr = i & 511;
                int r = rr >> 3, c = rr & 7;
                cpa16(sn + 16384 + z * 8192 + swz128B(r, c),
                      Wall + (size_t)z * NC * NC + (size_t)((kc + 1) * 64 + r) * NC + n0 + c * 8);
            }
            cpa_commit();
            asm volatile("cp.async.wait_group 1;");
        } else {
            asm volatile("cp.async.wait_group 0;");
        }
        __syncthreads();

        #pragma unroll
        for (int k16 = 0; k16 < 4; ++k16) {
            uint32_t a[2][4];
            ldsm4(a[0], st + swz128B(mw * 32 + lr,      k16 * 2 + hc));
            ldsm4(a[1], st + swz128B(mw * 32 + 16 + lr, k16 * 2 + hc));
            #pragma unroll
            for (int z = 0; z < 3; ++z) {
                uint32_t bw[2][4];
                #pragma unroll
                for (int ng = 0; ng < 2; ++ng)
                    ldsm4t(bw[ng], st + 16384 + z * 8192 +
                           swz128B(k16 * 16 + lr, nw * 4 + ng * 2 + hc));
                #pragma unroll
                for (int mt = 0; mt < 2; ++mt)
                    #pragma unroll
                    for (int nt = 0; nt < 4; ++nt) {
                        const uint32_t* bp = bw[nt >> 1];
                        uint32_t bb0 = (nt & 1) ? bp[2] : bp[0];
                        uint32_t bb1 = (nt & 1) ? bp[3] : bp[1];
                        mma_f16(acc[z][mt][nt], a[mt], bb0, bb1);
                    }
            }
        }
        __syncthreads();
    }

    int g = lane >> 2, t2 = (lane & 3) * 2;
    #pragma unroll
    for (int z = 0; z < 3; ++z) {
        const float* bias = (z == 0) ? b0 : (z == 1) ? b1 : b2;
        f16* out = (z == 0) ? o0 : (z == 1) ? o1 : o2;
        #pragma unroll
        for (int mt = 0; mt < 2; ++mt) {
            #pragma unroll
            for (int nt = 0; nt < 4; ++nt) {
                int row = m0 + mw * 32 + mt * 16 + g;
                int col = n0 + nw * 32 + nt * 8 + t2;
                float b0f = bias[col], b1f = bias[col + 1];
                float2 lo = h2f2(acc[z][mt][nt][0]);
                float2 hi = h2f2(acc[z][mt][nt][1]);
                *reinterpret_cast<uint32_t*>(out + (size_t)row * NC + col) =
                    pack_h2(lo.x + b0f, lo.y + b1f);
                *reinterpret_cast<uint32_t*>(out + (size_t)(row + 8) * NC + col) =
                    pack_h2(hi.x + b0f, hi.y + b1f);
            }
        }
    }
}

// ---------------- mm_out: BM=128, BN=64, Kc=64, fp32 accum (round-14) ---------------
#define GEMM_SMEM 49152

__global__ __launch_bounds__(256, 3) void mm_out(const f16* __restrict__ A,
                                                 const f16* __restrict__ W,
                                                 const float* __restrict__ bias,
                                                 const float* __restrict__ resid,
                                                 float* __restrict__ out) {
    extern __shared__ char smc[];
    int m0 = blockIdx.x * 128, n0 = blockIdx.y * 64;
    const uint32_t sb = smem_u32(smc);
    const uint32_t sa[2] = { sb,         sb + 24576 };
    const uint32_t sw[2] = { sb + 16384, sb + 40960 };
    int tid = threadIdx.x, lane = tid & 31, wid = tid >> 5;
    int mw = wid >> 1, nw = wid & 1;
    int lr = lane & 15, hc = lane >> 4;

    for (int i = tid; i < 1024; i += 256) {
        int r = i >> 3, c = i & 7;
        cpa16(sa[0] + swz128B(r, c), A + (size_t)(m0 + r) * NC + c * 8);
    }
    for (int i = tid; i < 512; i += 256) {
        int r = i >> 3, c = i & 7;
        cpa16(sw[0] + swz128B(r, c), W + (size_t)r * NC + n0 + c * 8);
    }
    cpa_commit();

    float acc[2][4][4] = {};
    #pragma unroll
    for (int kc = 0; kc < 4; ++kc) {
        const int buf = kc & 1;
        if (kc < 3) {
            const f16* Ak = A + (kc + 1) * 64;
            const f16* Wk = W + (size_t)(kc + 1) * 64 * NC;
            for (int i = tid; i < 1024; i += 256) {
                int r = i >> 3, c = i & 7;
                cpa16(sa[buf ^ 1] + swz128B(r, c), Ak + (size_t)(m0 + r) * NC + c * 8);
            }
            for (int i = tid; i < 512; i += 256) {
                int r = i >> 3, c = i & 7;
                cpa16(sw[buf ^ 1] + swz128B(r, c), Wk + (size_t)r * NC + n0 + c * 8);
            }
            cpa_commit();
            asm volatile("cp.async.wait_group 1;");
        } else {
            asm volatile("cp.async.wait_group 0;");
        }
        __syncthreads();

        #pragma unroll
        for (int k16 = 0; k16 < 4; ++k16) {
            uint32_t a[2][4];
            ldsm4(a[0], sa[buf] + swz128B(mw * 32 + lr,      k16 * 2 + hc));
            ldsm4(a[1], sa[buf] + swz128B(mw * 32 + 16 + lr, k16 * 2 + hc));
            uint32_t bw[2][4];
            #pragma unroll
            for (int ng = 0; ng < 2; ++ng)
                ldsm4t(bw[ng], sw[buf] + swz128B(k16 * 16 + lr, nw * 4 + ng * 2 + hc));
            #pragma unroll
            for (int mt = 0; mt < 2; ++mt)
                #pragma unroll
                for (int nt = 0; nt < 4; ++nt) {
                    const uint32_t* bp = bw[nt >> 1];
                    uint32_t bb0 = (nt & 1) ? bp[2] : bp[0];
                    uint32_t bb1 = (nt & 1) ? bp[3] : bp[1];
                    mma_f32(acc[mt][nt], a[mt], bb0, bb1);
                }
        }
        __syncthreads();
    }

    int g = lane >> 2, t2 = (lane & 3) * 2;
    #pragma unroll
    for (int mt = 0; mt < 2; ++mt) {
        #pragma unroll
        for (int nt = 0; nt < 4; ++nt) {
            int row = m0 + mw * 32 + mt * 16 + g;
            int col = n0 + nw * 32 + nt * 8 + t2;
            float b0f = bias[col], b1f = bias[col + 1];
            float2 r0 = *reinterpret_cast<const float2*>(resid + (size_t)row * NC + col);
            float2 r1 = *reinterpret_cast<const float2*>(resid + (size_t)(row + 8) * NC + col);
            *reinterpret_cast<float2*>(out + (size_t)row * NC + col) =
                make_float2(acc[mt][nt][0] + b0f + r0.x, acc[mt][nt][1] + b1f + r0.y);
            *reinterpret_cast<float2*>(out + (size_t)(row + 8) * NC + col) =
                make_float2(acc[mt][nt][2] + b0f + r1.x, acc[mt][nt][3] + b1f + r1.y);
        }
    }
}

// ---------------- flash attention: 512 thr, BN=128, single-buffered K/V -------------
// (round-13 proven; unchanged)
#define AO_Q  0
#define AO_K  65536
#define AO_V  131072
#define AO_P  196608
#define AO_L  229376
#define ATTN_SMEM 231424

__global__ __launch_bounds__(512, 1) void attn_hmma(const f16* __restrict__ gq,
                                                    const f16* __restrict__ gk,
                                                    const f16* __restrict__ gv,
                                                    f16* __restrict__ gao) {
    extern __shared__ char smc[];
    const uint32_t sb = smem_u32(smc);
    float* lsh = reinterpret_cast<float*>(smc + AO_L);

    const int b = blockIdx.y, q0 = blockIdx.x * 128;
    const int tid = threadIdx.x, lane = tid & 31, wid = tid >> 5;
    const int mw = wid >> 2, nw = wid & 3;
    const int pw = wid >> 3, pn = wid & 7;
    const int lr = lane & 15, hc = lane >> 4;
    const int g = lane >> 2, t2 = (lane & 3) * 2;
    const uint32_t SC2 = pack_h2(0.09016844006f, 0.09016844006f);

    const f16* qg = gq + ((size_t)b * NS + q0) * NC;
    const f16* kg = gk + (size_t)b * NS * NC;
    const f16* vg = gv + (size_t)b * NS * NC;

    for (int i = tid; i < 4096; i += 512) {
        int r = i >> 5, c = i & 31;
        cpa16(sb + AO_Q + swz512B(r, c), qg + (size_t)r * NC + c * 8);
    }
    for (int i = tid; i < 4096; i += 512) {
        int r = i >> 5, c = i & 31;
        cpa16(sb + AO_K + swz512B(r, c), kg + (size_t)r * NC + c * 8);
    }
    cpa_commit();
    asm volatile("cp.async.wait_group 0;");
    __syncthreads();

    uint32_t O16[4][4][2];
    #pragma unroll
    for (int mt = 0; mt < 4; ++mt)
        #pragma unroll
        for (int nt = 0; nt < 4; ++nt) { O16[mt][nt][0] = 0u; O16[mt][nt][1] = 0u; }
    float lacc[4] = {0.f, 0.f, 0.f, 0.f};

    for (int t = 0; t < KTILES; ++t) {
        __syncthreads();

        {
            const f16* vs = vg + (size_t)t * 128 * NC;
            for (int i = tid; i < 4096; i += 512) {
                int r = i >> 5, c = i & 31;
                cpa16(sb + AO_V + swz512B(r, c), vs + (size_t)r * NC + c * 8);
            }
            cpa_commit();
        }

        {
            uint32_t s16[2][4][2];
            #pragma unroll
            for (int mi = 0; mi < 2; ++mi)
                #pragma unroll
                for (int nt = 0; nt < 4; ++nt) { s16[mi][nt][0] = 0u; s16[mi][nt][1] = 0u; }
            #pragma unroll
            for (int k16 = 0; k16 < 16; ++k16) {
                uint32_t a[2][4];
                ldsm4(a[0], sb + AO_Q + swz512B(mw * 32 + lr,      k16 * 2 + hc));
                ldsm4(a[1], sb + AO_Q + swz512B(mw * 32 + 16 + lr, k16 * 2 + hc));
                #pragma unroll
                for (int ng = 0; ng < 2; ++ng) {
                    uint32_t kf[4];
                    ldsm4(kf, sb + AO_K + swz512B(nw * 32 + ng * 16 + lr, k16 * 2 + hc));
                    mma_f16(s16[0][2 * ng],     a[0], kf[0], kf[2]);
                    mma_f16(s16[0][2 * ng + 1], a[0], kf[1], kf[3]);
                    mma_f16(s16[1][2 * ng],     a[1], kf[0], kf[2]);
                    mma_f16(s16[1][2 * ng + 1], a[1], kf[1], kf[3]);
                }
            }
            #pragma unroll
            for (int mi = 0; mi < 2; ++mi) {
                int row0 = mw * 32 + mi * 16 + g;
                uint32_t lp[2] = {0u, 0u};
                #pragma unroll
                for (int nt = 0; nt < 4; ++nt) {
                    int chunk = nw * 4 + nt;
                    #pragma unroll
                    for (int h = 0; h < 2; ++h) {
                        uint32_t p;
                        asm("mul.f16x2 %0,%1,%2;" : "=r"(p) : "r"(s16[mi][nt][h]), "r"(SC2));
                        asm("ex2.approx.f16x2 %0,%1;" : "=r"(p) : "r"(p));
                        lp[h] = hadd2u(lp[h], p);
                        *reinterpret_cast<uint32_t*>(smc + AO_P +
                            swz256B(row0 + h * 8, chunk) + t2 * 2) = p;
                    }
                }
                #pragma unroll
                for (int h = 0; h < 2; ++h) {
                    float2 lf = h2f2(lp[h]);
                    lacc[mi * 2 + h] += lf.x + lf.y;
                }
            }
        }

        asm volatile("cp.async.wait_group 0;");
        __syncthreads();

        if (t + 1 < KTILES) {
            const f16* ks = kg + (size_t)(t + 1) * 128 * NC;
            for (int i = tid; i < 4096; i += 512) {
                int r = i >> 5, c = i & 31;
                cpa16(sb + AO_K + swz512B(r, c), ks + (size_t)r * NC + c * 8);
            }
            cpa_commit();
        }

        #pragma unroll
        for (int k16 = 0; k16 < 8; ++k16) {
            uint32_t pa[4][4];
            #pragma unroll
            for (int mt = 0; mt < 4; ++mt)
                ldsm4(pa[mt], sb + AO_P + swz256B(pw * 64 + mt * 16 + lr, k16 * 2 + hc));
            uint32_t vf[2][4];
            #pragma unroll
            for (int d = 0; d < 2; ++d)
                ldsm4t(vf[d], sb + AO_V + swz512B(k16 * 16 + lr, pn * 4 + d * 2 + hc));
            #pragma unroll
            for (int mt = 0; mt < 4; ++mt)
                #pragma unroll
                for (int nt = 0; nt < 4; ++nt) {
                    const uint32_t* bp = vf[nt >> 1];
                    uint32_t bb0 = (nt & 1) ? bp[2] : bp[0];
                    uint32_t bb1 = (nt & 1) ? bp[3] : bp[1];
                    mma_f16(O16[mt][nt], pa[mt], bb0, bb1);
                }
        }

        asm volatile("cp.async.wait_group 0;");
    }

    #pragma unroll
    for (int i = 0; i < 4; ++i) {
        lacc[i] += __shfl_xor_sync(0xffffffffu, lacc[i], 1);
        lacc[i] += __shfl_xor_sync(0xffffffffu, lacc[i], 2);
    }
    __syncthreads();
    if ((lane & 3) == 0) {
        lsh[(mw * 32 + g)      * 4 + nw] = lacc[0];
        lsh[(mw * 32 + 8 + g)  * 4 + nw] = lacc[1];
        lsh[(mw * 32 + 16 + g) * 4 + nw] = lacc[2];
        lsh[(mw * 32 + 24 + g) * 4 + nw] = lacc[3];
    }
    __syncthreads();

    #pragma unroll
    for (int mt = 0; mt < 4; ++mt) {
        #pragma unroll
        for (int h = 0; h < 2; ++h) {
            int row = pw * 64 + mt * 16 + h * 8 + g;
            float l = lsh[row * 4] + lsh[row * 4 + 1] + lsh[row * 4 + 2] + lsh[row * 4 + 3];
            float linv = 1.f / l;
            f16* op = gao + ((size_t)b * NS + q0 + row) * NC + pn * 32;
            #pragma unroll
            for (int nt = 0; nt < 4; ++nt) {
                float2 of = h2f2(O16[mt][nt][h]);
                *reinterpret_cast<uint32_t*>(op + nt * 8 + t2) =
                    pack_h2(of.x * linv, of.y * linv);
            }
        }
    }
}

// ---------------- launch ------------------------------------------------------------
extern "C" void kernel_launch(void* const* d_in, const int* in_sizes, int n_in,
                              void* d_out, int out_size) {
    const float* x      = (const float*)d_in[0];
    const float* gscale = (const float*)d_in[1];
    const float* gbias  = (const float*)d_in[2];
    const float* wq = (const float*)d_in[3];
    const float* bq = (const float*)d_in[4];
    const float* wk = (const float*)d_in[5];
    const float* bk = (const float*)d_in[6];
    const float* wv = (const float*)d_in[7];
    const float* bv = (const float*)d_in[8];
    const float* wo = (const float*)d_in[9];
    const float* bo = (const float*)d_in[10];

    f16 *hnb, *qb, *kb, *vb, *aob, *wb;
    cudaGetSymbolAddress((void**)&hnb, g_hnb);
    cudaGetSymbolAddress((void**)&qb,  g_qb);
    cudaGetSymbolAddress((void**)&kb,  g_kb);
    cudaGetSymbolAddress((void**)&vb,  g_vb);
    cudaGetSymbolAddress((void**)&aob, g_aob);
    cudaGetSymbolAddress((void**)&wb,  g_wb);

    cudaFuncSetAttribute(mm_qkv_fused, cudaFuncAttributeMaxDynamicSharedMemorySize, QKV_SMEM);
    cudaFuncSetAttribute(mm_out, cudaFuncAttributeMaxDynamicSharedMemorySize, GEMM_SMEM);
    cudaFuncSetAttribute(attn_hmma, cudaFuncAttributeMaxDynamicSharedMemorySize, ATTN_SMEM);

    gn_stats_kernel<<<NB * NG, 256>>>(x);
    gn_apply_wconv<<<8192 + 1024, 256>>>(x, gscale, gbias, wq, wk, wv, wo, wb);

    mm_qkv_fused<<<dim3(NB * NS / 128, NC / 64), 256, QKV_SMEM>>>(hnb, wb, bq, bk, bv, qb, kb, vb);

    attn_hmma<<<dim3(NS / 128, NB), 512, ATTN_SMEM>>>(qb, kb, vb, aob);

    mm_out<<<dim3(NB * NS / 128, NC / 64), 256, GEMM_SMEM>>>(aob, wb + 3 * NC * NC, bo, x, (float*)d_out);
}